// round 5
// baseline (speedup 1.0000x reference)
#include <cuda_runtime.h>
#include <cstdint>

#define FULL 0xffffffffu

static constexpr int S = 8;
static constexpr int N = 4096;
static constexpr int M = 64;
static constexpr int SN = S * N;

__device__ float  g_v8[32];      // v8[tt][8] = td_table[tt] @ en1_w
__device__ float4 g_pos4[SN];    // (x, y, z, type)

// ---------------------------------------------------------------------------
// Prepass: pack positions+type into float4; block 0 collapses species MLPs.
// ---------------------------------------------------------------------------
__global__ void pack_kernel(
    const float* __restrict__ pos, const int* __restrict__ types,
    const float* __restrict__ es1_w, const float* __restrict__ es1_b,
    const float* __restrict__ es2_w, const float* __restrict__ es2_b,
    const float* __restrict__ fs1_w, const float* __restrict__ fs1_b,
    const float* __restrict__ fs2_w, const float* __restrict__ fs2_b,
    const float* __restrict__ en1_w)
{
    const int i = blockIdx.x * blockDim.x + threadIdx.x;
    if (i < SN)
        g_pos4[i] = make_float4(pos[3 * i], pos[3 * i + 1], pos[3 * i + 2],
                                (float)types[i]);

    if (blockIdx.x == 0 && threadIdx.x < 4) {
        const int tt = threadIdx.x;
        const float ti = (float)(tt >> 1);
        const float tj = (float)(tt & 1);

        float e[4];
        {
            float h[4];
            #pragma unroll
            for (int k = 0; k < 4; k++)
                h[k] = fmaxf(ti * es1_w[k] + tj * es1_w[4 + k] + es1_b[k], 0.f);
            #pragma unroll
            for (int k = 0; k < 4; k++) {
                float a = es2_b[k];
                #pragma unroll
                for (int j = 0; j < 4; j++) a += h[j] * es2_w[j * 4 + k];
                e[k] = a;
            }
        }
        {
            float h[4];
            #pragma unroll
            for (int k = 0; k < 4; k++)
                h[k] = fmaxf(tj * es1_w[k] + ti * es1_w[4 + k] + es1_b[k], 0.f);
            #pragma unroll
            for (int k = 0; k < 4; k++) {
                float a = es2_b[k];
                #pragma unroll
                for (int j = 0; j < 4; j++) a += h[j] * es2_w[j * 4 + k];
                e[k] += a;
            }
        }
        float y[4];
        #pragma unroll
        for (int k = 0; k < 4; k++) {
            float a = fs1_b[k];
            #pragma unroll
            for (int j = 0; j < 4; j++) a += e[j] * fs1_w[j * 4 + k];
            y[k] = fmaxf(a, 0.f);
        }
        float td[4];
        #pragma unroll
        for (int k = 0; k < 4; k++) {
            float a = fs2_b[k];
            #pragma unroll
            for (int j = 0; j < 4; j++) a += y[j] * fs2_w[j * 4 + k];
            td[k] = a;
        }
        #pragma unroll
        for (int o = 0; o < 8; o++) {
            float a = 0.f;
            #pragma unroll
            for (int d = 0; d < 4; d++) a += td[d] * en1_w[d * 8 + o];
            g_v8[tt * 8 + o] = a;
        }
    }
}

// ---------------------------------------------------------------------------
// Main kernel: one warp per atom; compacted survivors; 8 survivors/iteration
// (most atoms need exactly one iteration). 64-reg budget for 50% occupancy.
// ---------------------------------------------------------------------------
__global__ __launch_bounds__(256, 4)
void descriptor_kernel(
    const int*   __restrict__ neigh,   // [S,N,M]
    const float* __restrict__ en1_b,   // [8]
    const float* __restrict__ en2_w,   // [8,16]
    const float* __restrict__ en2_b,   // [16]
    const float* __restrict__ en3_w,   // [16,32]
    const float* __restrict__ en3_b,   // [32]
    float*       __restrict__ out)     // [S,N,32,16]
{
    __shared__ float4 sh_v8q[8];            // [tt*2 + half]
    __shared__ float4 sh_w2q[32];           // en2_w as float4 rows
    __shared__ float4 sh_rt[8][72];         // compacted survivors (+7 pad)
    __shared__ int    sh_tt[8][72];
    __shared__ float  sh_h2[8][2][8][16];   // [warp][parity][survivor][col]

    const int tid  = threadIdx.x;
    const int lane = tid & 31;
    const int w    = tid >> 5;

    if (tid < 32)  ((float*)sh_v8q)[tid] = g_v8[tid];
    if (tid < 128) ((float*)sh_w2q)[tid] = en2_w[tid];

    // lane g owns en3 column g; lane serves survivor (lane>>2) with 4 h2 cols
    const int g   = lane;
    const int ch  = lane & 3;
    const int c0  = ch * 4;
    float W3[16], b1r[8];
    #pragma unroll
    for (int j = 0; j < 16; j++) W3[j] = __ldg(&en3_w[j * 32 + g]);
    #pragma unroll
    for (int j = 0; j < 8; j++)  b1r[j] = __ldg(&en1_b[j]);
    const float4 b2q = *reinterpret_cast<const float4*>(&en2_b[c0]);
    const float  b3g = __ldg(&en3_b[g]);
    __syncthreads();

    const int atom  = blockIdx.x * 8 + w;     // atom = s*N + n
    const int s_idx = atom >> 12;             // N = 4096

    const float4 pi = g_pos4[atom];
    const int    ti2 = 2 * (int)pi.w;

    // -------- Phase 1: geometry + ballot-popc compaction --------
    const int2 nb2 = reinterpret_cast<const int2*>(neigh + atom * M)[lane];
    int cnt = 0;
    #pragma unroll
    for (int p = 0; p < 2; p++) {
        const int nb = (p == 0) ? nb2.x : nb2.y;
        const int jj = (nb < 0) ? 0 : nb;
        const int bj = (s_idx << 12) + jj;

        const float4 pj = g_pos4[bj];

        float dx = pj.x - pi.x; dx -= 20.f * rintf(dx * 0.05f);
        float dy = pj.y - pi.y; dy -= 20.f * rintf(dy * 0.05f);
        float dz = pj.z - pi.z; dz -= 20.f * rintf(dz * 0.05f);

        const float r2   = fmaf(dx, dx, fmaf(dy, dy, fmaf(dz, dz, 1e-12f)));
        const float rinv = rsqrtf(r2);
        const float r    = r2 * rinv;

        float sw;
        if (r < 2.f)      sw = 1.f;
        else if (r < 6.f) sw = fmaf(0.5f, cospif((r - 2.f) * 0.25f), 0.5f);
        else              sw = 0.f;

        const float s_ij  = (nb < 0) ? 0.f : sw * rinv;
        const float srinv = s_ij * rinv;

        const bool alive = (s_ij != 0.f);
        const unsigned bb = __ballot_sync(FULL, alive);
        if (alive) {
            const int pos = cnt + __popc(bb & ((1u << lane) - 1u));
            sh_rt[w][pos] = make_float4(s_ij, dx * srinv, dy * srinv, dz * srinv);
            sh_tt[w][pos] = ti2 + (int)pj.w;
        }
        cnt += __popc(bb);
    }
    // zero-pad 7 slots so 8-wide iterations are safe
    if (lane < 7) {
        sh_rt[w][cnt + lane] = make_float4(0.f, 0.f, 0.f, 0.f);
        sh_tt[w][cnt + lane] = 0;
    }
    __syncwarp();

    float A0 = 0.f, A1 = 0.f, A2 = 0.f, A3 = 0.f;
    const int qs = lane >> 2;    // survivor slot this lane serves
    int par = 0;

    // -------- Phase 2: 8 survivors per iteration --------
    for (int i = 0; i < cnt; i += 8) {
        const float4 rt = sh_rt[w][i + qs];
        const int    tt = sh_tt[w][i + qs];
        const float4 v8lo = sh_v8q[tt * 2 + 0];
        const float4 v8hi = sh_v8q[tt * 2 + 1];
        const float  sm   = rt.x;

        // layer 1 (8 outputs, shared by this lane's 4 columns)
        float h1[8];
        h1[0] = fmaxf(fmaf(sm, v8lo.x, b1r[0]), 0.f);
        h1[1] = fmaxf(fmaf(sm, v8lo.y, b1r[1]), 0.f);
        h1[2] = fmaxf(fmaf(sm, v8lo.z, b1r[2]), 0.f);
        h1[3] = fmaxf(fmaf(sm, v8lo.w, b1r[3]), 0.f);
        h1[4] = fmaxf(fmaf(sm, v8hi.x, b1r[4]), 0.f);
        h1[5] = fmaxf(fmaf(sm, v8hi.y, b1r[5]), 0.f);
        h1[6] = fmaxf(fmaf(sm, v8hi.z, b1r[6]), 0.f);
        h1[7] = fmaxf(fmaf(sm, v8hi.w, b1r[7]), 0.f);

        // layer 2: 4 columns c0..c0+3, weights streamed from shared
        float4 h2 = b2q;
        #pragma unroll
        for (int j = 0; j < 8; j++) {
            const float4 w2 = sh_w2q[j * 4 + ch];
            h2.x = fmaf(h1[j], w2.x, h2.x);
            h2.y = fmaf(h1[j], w2.y, h2.y);
            h2.z = fmaf(h1[j], w2.z, h2.z);
            h2.w = fmaf(h1[j], w2.w, h2.w);
        }
        h2.x = fmaxf(h2.x, 0.f); h2.y = fmaxf(h2.y, 0.f);
        h2.z = fmaxf(h2.z, 0.f); h2.w = fmaxf(h2.w, 0.f);

        *reinterpret_cast<float4*>(&sh_h2[w][par][qs][c0]) = h2;
        __syncwarp();

        // layer 3 + A accumulation for all 8 survivors (uniform broadcasts)
        #pragma unroll
        for (int sv = 0; sv < 8; sv++) {
            const float4* hq = reinterpret_cast<const float4*>(sh_h2[w][par][sv]);
            float G = b3g;
            #pragma unroll
            for (int q = 0; q < 4; q++) {
                const float4 hv = hq[q];
                G = fmaf(hv.x, W3[4 * q + 0], G);
                G = fmaf(hv.y, W3[4 * q + 1], G);
                G = fmaf(hv.z, W3[4 * q + 2], G);
                G = fmaf(hv.w, W3[4 * q + 3], G);
            }
            const float4 rs = sh_rt[w][i + sv];
            A0 = fmaf(G, rs.x, A0);
            A1 = fmaf(G, rs.y, A1);
            A2 = fmaf(G, rs.z, A2);
            A3 = fmaf(G, rs.w, A3);
        }
        par ^= 1;
    }

    // -------- Epilogue: D[g][k] = sum_d A[g][d]*A[k][d], k < 16 --------
    __syncwarp();
    sh_rt[w][lane] = make_float4(A0, A1, A2, A3);
    __syncwarp();

    float d[16];
    #pragma unroll
    for (int k = 0; k < 16; k++) {
        const float4 B = sh_rt[w][k];
        d[k] = fmaf(A0, B.x, fmaf(A1, B.y, fmaf(A2, B.z, A3 * B.w)));
    }

    float4* o4 = reinterpret_cast<float4*>(out + (size_t)atom * 512 + g * 16);
    o4[0] = make_float4(d[0],  d[1],  d[2],  d[3]);
    o4[1] = make_float4(d[4],  d[5],  d[6],  d[7]);
    o4[2] = make_float4(d[8],  d[9],  d[10], d[11]);
    o4[3] = make_float4(d[12], d[13], d[14], d[15]);
}

// ---------------------------------------------------------------------------
extern "C" void kernel_launch(void* const* d_in, const int* in_sizes, int n_in,
                              void* d_out, int out_size)
{
    const float* inputs      = (const float*)d_in[0];
    const int*   input_types = (const int*)  d_in[1];
    const int*   neigh_list  = (const int*)  d_in[2];
    const float* es1_w = (const float*)d_in[3];
    const float* es1_b = (const float*)d_in[4];
    const float* es2_w = (const float*)d_in[5];
    const float* es2_b = (const float*)d_in[6];
    const float* fs1_w = (const float*)d_in[7];
    const float* fs1_b = (const float*)d_in[8];
    const float* fs2_w = (const float*)d_in[9];
    const float* fs2_b = (const float*)d_in[10];
    const float* en1_w = (const float*)d_in[11];
    const float* en1_b = (const float*)d_in[12];
    const float* en2_w = (const float*)d_in[13];
    const float* en2_b = (const float*)d_in[14];
    const float* en3_w = (const float*)d_in[15];
    const float* en3_b = (const float*)d_in[16];
    float* out = (float*)d_out;

    pack_kernel<<<(SN + 255) / 256, 256>>>(inputs, input_types,
                                           es1_w, es1_b, es2_w, es2_b,
                                           fs1_w, fs1_b, fs2_w, fs2_b, en1_w);

    descriptor_kernel<<<SN / 8, 256>>>(neigh_list,
                                       en1_b, en2_w, en2_b, en3_w, en3_b,
                                       out);
}

// round 6
// speedup vs baseline: 1.0921x; 1.0921x over previous
#include <cuda_runtime.h>
#include <cstdint>

#define FULL 0xffffffffu

static constexpr int S = 8;
static constexpr int N = 4096;
static constexpr int M = 64;
static constexpr int SN = S * N;

__device__ float  g_v8[32];      // v8[tt][8] = td_table[tt] @ en1_w
__device__ float4 g_pos4[SN];    // (x, y, z, type)

// ---------------------------------------------------------------------------
// Prepass: pack positions+type into float4 (4 atoms/thread, vectorized);
// block 0 collapses species MLPs into the v8 table.
// ---------------------------------------------------------------------------
__global__ void pack_kernel(
    const float* __restrict__ pos, const int* __restrict__ types,
    const float* __restrict__ es1_w, const float* __restrict__ es1_b,
    const float* __restrict__ es2_w, const float* __restrict__ es2_b,
    const float* __restrict__ fs1_w, const float* __restrict__ fs1_b,
    const float* __restrict__ fs2_w, const float* __restrict__ fs2_b,
    const float* __restrict__ en1_w)
{
    const int idx = blockIdx.x * blockDim.x + threadIdx.x;
    if (idx < SN / 4) {
        const float4* pv = reinterpret_cast<const float4*>(pos) + idx * 3;
        const float4 a = pv[0], b = pv[1], c = pv[2];
        const int4 t = reinterpret_cast<const int4*>(types)[idx];
        float4* o = g_pos4 + idx * 4;
        o[0] = make_float4(a.x, a.y, a.z, (float)t.x);
        o[1] = make_float4(a.w, b.x, b.y, (float)t.y);
        o[2] = make_float4(b.z, b.w, c.x, (float)t.z);
        o[3] = make_float4(c.y, c.z, c.w, (float)t.w);
    }

    if (blockIdx.x == 0 && threadIdx.x < 4) {
        const int tt = threadIdx.x;
        const float ti = (float)(tt >> 1);
        const float tj = (float)(tt & 1);

        float e[4];
        {
            float h[4];
            #pragma unroll
            for (int k = 0; k < 4; k++)
                h[k] = fmaxf(ti * es1_w[k] + tj * es1_w[4 + k] + es1_b[k], 0.f);
            #pragma unroll
            for (int k = 0; k < 4; k++) {
                float aa = es2_b[k];
                #pragma unroll
                for (int j = 0; j < 4; j++) aa += h[j] * es2_w[j * 4 + k];
                e[k] = aa;
            }
        }
        {
            float h[4];
            #pragma unroll
            for (int k = 0; k < 4; k++)
                h[k] = fmaxf(tj * es1_w[k] + ti * es1_w[4 + k] + es1_b[k], 0.f);
            #pragma unroll
            for (int k = 0; k < 4; k++) {
                float aa = es2_b[k];
                #pragma unroll
                for (int j = 0; j < 4; j++) aa += h[j] * es2_w[j * 4 + k];
                e[k] += aa;
            }
        }
        float y[4];
        #pragma unroll
        for (int k = 0; k < 4; k++) {
            float aa = fs1_b[k];
            #pragma unroll
            for (int j = 0; j < 4; j++) aa += e[j] * fs1_w[j * 4 + k];
            y[k] = fmaxf(aa, 0.f);
        }
        float td[4];
        #pragma unroll
        for (int k = 0; k < 4; k++) {
            float aa = fs2_b[k];
            #pragma unroll
            for (int j = 0; j < 4; j++) aa += y[j] * fs2_w[j * 4 + k];
            td[k] = aa;
        }
        #pragma unroll
        for (int o = 0; o < 8; o++) {
            float aa = 0.f;
            #pragma unroll
            for (int d = 0; d < 4; d++) aa += td[d] * en1_w[d * 8 + o];
            g_v8[tt * 8 + o] = aa;
        }
    }
}

// ---------------------------------------------------------------------------
// Main kernel: one warp per atom; compacted survivors with tt packed into
// s_ij mantissa LSBs; 4 survivors per iteration with uniform live limit.
// ---------------------------------------------------------------------------
__global__ __launch_bounds__(256, 3)
void descriptor_kernel(
    const int*   __restrict__ neigh,   // [S,N,M]
    const float* __restrict__ en1_b,   // [8]
    const float* __restrict__ en2_w,   // [8,16]
    const float* __restrict__ en2_b,   // [16]
    const float* __restrict__ en3_w,   // [16,32]
    const float* __restrict__ en3_b,   // [32]
    float*       __restrict__ out)     // [S,N,32,16]
{
    __shared__ float4 sh_v8q[8];            // [tt*2 + half]
    __shared__ float4 sh_rt[8][64];         // compacted survivors
    __shared__ float  sh_h2[8][2][4][16];   // [warp][parity][survivor][col]

    const int tid  = threadIdx.x;
    const int lane = tid & 31;
    const int w    = tid >> 5;

    if (tid < 32) ((float*)sh_v8q)[tid] = g_v8[tid];

    // lane g owns en3 column g; lane owns en2 columns c0, c0+1 of its quarter
    const int g  = lane;
    const int c0 = (lane & 7) * 2;
    float  W3[16], b1r[8];
    float2 W2[8];
    #pragma unroll
    for (int j = 0; j < 16; j++) W3[j] = __ldg(&en3_w[j * 32 + g]);
    #pragma unroll
    for (int j = 0; j < 8; j++)
        W2[j] = *reinterpret_cast<const float2*>(&en2_w[j * 16 + c0]);
    #pragma unroll
    for (int j = 0; j < 8; j++)  b1r[j] = __ldg(&en1_b[j]);
    const float2 b2 = *reinterpret_cast<const float2*>(&en2_b[c0]);
    const float  b3g = __ldg(&en3_b[g]);
    __syncthreads();

    const int atom  = blockIdx.x * 8 + w;     // atom = s*N + n
    const int base  = atom & ~4095;           // snapshot base (N = 4096)

    const float4 pi = g_pos4[atom];
    const int    ti2 = 2 * (int)pi.w;

    // -------- Phase 1: prefetch both gathers, then geometry + compaction ----
    const int2 nb2 = reinterpret_cast<const int2*>(neigh + atom * M)[lane];
    const int jj0 = (nb2.x < 0) ? 0 : nb2.x;
    const int jj1 = (nb2.y < 0) ? 0 : nb2.y;
    const float4 pj0 = g_pos4[base + jj0];
    const float4 pj1 = g_pos4[base + jj1];

    int cnt = 0;
    #pragma unroll
    for (int p = 0; p < 2; p++) {
        const int    nb = (p == 0) ? nb2.x : nb2.y;
        const float4 pj = (p == 0) ? pj0 : pj1;

        float dx = pj.x - pi.x; dx -= 20.f * rintf(dx * 0.05f);
        float dy = pj.y - pi.y; dy -= 20.f * rintf(dy * 0.05f);
        float dz = pj.z - pi.z; dz -= 20.f * rintf(dz * 0.05f);

        const float r2   = fmaf(dx, dx, fmaf(dy, dy, fmaf(dz, dz, 1e-12f)));
        const float rinv = rsqrtf(r2);
        const float r    = r2 * rinv;

        float sw;
        if (r < 2.f)      sw = 1.f;
        else if (r < 6.f) sw = fmaf(0.5f, cospif((r - 2.f) * 0.25f), 0.5f);
        else              sw = 0.f;

        const float s_ij  = (nb < 0) ? 0.f : sw * rinv;
        const float srinv = s_ij * rinv;

        const bool alive = (s_ij != 0.f);
        const unsigned bb = __ballot_sync(FULL, alive);
        if (alive) {
            // pack type-pair into 2 mantissa LSBs of s_ij (|ds/s| <= 2^-22)
            const unsigned se = (__float_as_uint(s_ij) & ~3u)
                              | (unsigned)(ti2 + (int)pj.w);
            const int pos = cnt + __popc(bb & ((1u << lane) - 1u));
            sh_rt[w][pos] = make_float4(__uint_as_float(se),
                                        dx * srinv, dy * srinv, dz * srinv);
        }
        cnt += __popc(bb);
    }
    __syncwarp();

    float A0 = 0.f, A1 = 0.f, A2 = 0.f, A3 = 0.f;
    const int qs = lane >> 3;    // survivor slot this lane serves
    int par = 0;

    // -------- Phase 2: 4 survivors per iteration, uniform live limit --------
    for (int i = 0; i < cnt; i += 4) {
        const int   sl = min(i + qs, cnt - 1);
        const float4 rt = sh_rt[w][sl];
        const unsigned sb = __float_as_uint(rt.x);
        const int    tt = (int)(sb & 3u);
        const float4 v8lo = sh_v8q[tt * 2 + 0];
        const float4 v8hi = sh_v8q[tt * 2 + 1];
        const float  sm   = rt.x;

        // layer 1 (8 outputs shared by this lane's 2 columns)
        float h1[8];
        h1[0] = fmaxf(fmaf(sm, v8lo.x, b1r[0]), 0.f);
        h1[1] = fmaxf(fmaf(sm, v8lo.y, b1r[1]), 0.f);
        h1[2] = fmaxf(fmaf(sm, v8lo.z, b1r[2]), 0.f);
        h1[3] = fmaxf(fmaf(sm, v8lo.w, b1r[3]), 0.f);
        h1[4] = fmaxf(fmaf(sm, v8hi.x, b1r[4]), 0.f);
        h1[5] = fmaxf(fmaf(sm, v8hi.y, b1r[5]), 0.f);
        h1[6] = fmaxf(fmaf(sm, v8hi.z, b1r[6]), 0.f);
        h1[7] = fmaxf(fmaf(sm, v8hi.w, b1r[7]), 0.f);

        // layer 2: two columns (c0, c0+1)
        float ha = b2.x, hb = b2.y;
        #pragma unroll
        for (int j = 0; j < 8; j++) {
            ha = fmaf(h1[j], W2[j].x, ha);
            hb = fmaf(h1[j], W2[j].y, hb);
        }
        ha = fmaxf(ha, 0.f);
        hb = fmaxf(hb, 0.f);

        *reinterpret_cast<float2*>(&sh_h2[w][par][qs][c0]) = make_float2(ha, hb);
        __syncwarp();

        // layer 3 + A accumulation, only live slots (lim is warp-uniform)
        const int lim = min(4, cnt - i);
        const float (*hh)[16] = sh_h2[w][par];
        for (int sv = 0; sv < lim; sv++) {
            const float4* hq = reinterpret_cast<const float4*>(hh[sv]);
            float G = b3g;
            #pragma unroll
            for (int q = 0; q < 4; q++) {
                const float4 hv = hq[q];
                G = fmaf(hv.x, W3[4 * q + 0], G);
                G = fmaf(hv.y, W3[4 * q + 1], G);
                G = fmaf(hv.z, W3[4 * q + 2], G);
                G = fmaf(hv.w, W3[4 * q + 3], G);
            }
            const float4 rs = sh_rt[w][i + sv];
            A0 = fmaf(G, rs.x, A0);
            A1 = fmaf(G, rs.y, A1);
            A2 = fmaf(G, rs.z, A2);
            A3 = fmaf(G, rs.w, A3);
        }
        par ^= 1;
    }

    // -------- Epilogue: D[g][k] = sum_d A[g][d]*A[k][d], k < 16 --------
    __syncwarp();
    sh_rt[w][lane] = make_float4(A0, A1, A2, A3);
    __syncwarp();

    float d[16];
    #pragma unroll
    for (int k = 0; k < 16; k++) {
        const float4 B = sh_rt[w][k];
        d[k] = fmaf(A0, B.x, fmaf(A1, B.y, fmaf(A2, B.z, A3 * B.w)));
    }

    float4* o4 = reinterpret_cast<float4*>(out + (size_t)atom * 512 + g * 16);
    o4[0] = make_float4(d[0],  d[1],  d[2],  d[3]);
    o4[1] = make_float4(d[4],  d[5],  d[6],  d[7]);
    o4[2] = make_float4(d[8],  d[9],  d[10], d[11]);
    o4[3] = make_float4(d[12], d[13], d[14], d[15]);
}

// ---------------------------------------------------------------------------
extern "C" void kernel_launch(void* const* d_in, const int* in_sizes, int n_in,
                              void* d_out, int out_size)
{
    const float* inputs      = (const float*)d_in[0];
    const int*   input_types = (const int*)  d_in[1];
    const int*   neigh_list  = (const int*)  d_in[2];
    const float* es1_w = (const float*)d_in[3];
    const float* es1_b = (const float*)d_in[4];
    const float* es2_w = (const float*)d_in[5];
    const float* es2_b = (const float*)d_in[6];
    const float* fs1_w = (const float*)d_in[7];
    const float* fs1_b = (const float*)d_in[8];
    const float* fs2_w = (const float*)d_in[9];
    const float* fs2_b = (const float*)d_in[10];
    const float* en1_w = (const float*)d_in[11];
    const float* en1_b = (const float*)d_in[12];
    const float* en2_w = (const float*)d_in[13];
    const float* en2_b = (const float*)d_in[14];
    const float* en3_w = (const float*)d_in[15];
    const float* en3_b = (const float*)d_in[16];
    float* out = (float*)d_out;

    pack_kernel<<<(SN / 4 + 255) / 256, 256>>>(inputs, input_types,
                                               es1_w, es1_b, es2_w, es2_b,
                                               fs1_w, fs1_b, fs2_w, fs2_b,
                                               en1_w);

    descriptor_kernel<<<SN / 8, 256>>>(neigh_list,
                                       en1_b, en2_w, en2_b, en3_w, en3_b,
                                       out);
}